// round 1
// baseline (speedup 1.0000x reference)
#include <cuda_runtime.h>
#include <math.h>

// ---------------- problem constants ----------------
#define NB 32
#define HH 56
#define WW 56
#define CD 256
#define TOK (NB*HH*WW)          // 100352 tokens
#define HEADS 8
#define HDIM 32
#define HID 1024
#define WS 7
#define NWIN (TOK/(WS*WS))      // 2048 windows

// ---------------- scratch (static device globals; no runtime alloc) -------
__device__ float g_y   [(size_t)TOK * CD];       // LN1 output
__device__ float g_qkv [(size_t)TOK * 3 * CD];   // qkv, token layout
__device__ float g_o   [(size_t)TOK * CD];       // attention out, token layout
__device__ float g_x1  [(size_t)TOK * CD];       // after attn residual
__device__ float g_z   [(size_t)TOK * CD];       // LN2 output
__device__ float g_h1  [(size_t)TOK * HID];      // FFN hidden

// ---------------- LayerNorm: one warp per token (256 channels) -------------
__global__ __launch_bounds__(256) void ln_kernel(const float* __restrict__ in,
                                                 const float* __restrict__ g,
                                                 const float* __restrict__ b,
                                                 float* __restrict__ out) {
    int warp = (blockIdx.x * blockDim.x + threadIdx.x) >> 5;
    int lane = threadIdx.x & 31;
    if (warp >= TOK) return;
    const float* row = in + (size_t)warp * CD;
    float v[8];
    float s = 0.f;
#pragma unroll
    for (int k = 0; k < 8; k++) { v[k] = row[lane + k * 32]; s += v[k]; }
#pragma unroll
    for (int o = 16; o; o >>= 1) s += __shfl_xor_sync(0xffffffffu, s, o);
    float mean = s * (1.f / 256.f);
    float ss = 0.f;
#pragma unroll
    for (int k = 0; k < 8; k++) { float d = v[k] - mean; ss += d * d; }
#pragma unroll
    for (int o = 16; o; o >>= 1) ss += __shfl_xor_sync(0xffffffffu, ss, o);
    float inv = rsqrtf(ss * (1.f / 256.f) + 1e-5f);
    float* orow = out + (size_t)warp * CD;
#pragma unroll
    for (int k = 0; k < 8; k++) {
        int c = lane + k * 32;
        orow[c] = (v[k] - mean) * inv * g[c] + b[c];
    }
}

// ---------------- SGEMM: C[M,N] = A[M,K] * W[N,K]^T (+bias, epilogue) ------
// Exact-tile assumption: M%128==0, N%128==0, K%16==0 (holds for all calls).
enum { EP_BIAS = 0, EP_BIAS_RES = 1, EP_BIAS_GELU = 2 };

template <int EP>
__global__ __launch_bounds__(256) void sgemm_nt(const float* __restrict__ A,
                                                const float* __restrict__ W,
                                                const float* __restrict__ bias,
                                                const float* __restrict__ res,
                                                float* __restrict__ C,
                                                int M, int N, int K) {
    __shared__ float As[16][128];
    __shared__ float Bs[16][128];
    int tid  = threadIdx.x;
    int bm   = blockIdx.y * 128;
    int bn   = blockIdx.x * 128;
    int lrow = tid >> 2;            // 0..63
    int lk   = (tid & 3) << 2;      // 0,4,8,12

    float acc[8][8];
#pragma unroll
    for (int i = 0; i < 8; i++)
#pragma unroll
        for (int j = 0; j < 8; j++) acc[i][j] = 0.f;

    const float* Aptr = A + (size_t)(bm + lrow) * K + lk;
    const float* Wptr = W + (size_t)(bn + lrow) * K + lk;
    int tr = tid >> 4;              // 0..15
    int tc = tid & 15;              // 0..15

    for (int k0 = 0; k0 < K; k0 += 16) {
#pragma unroll
        for (int r = 0; r < 2; r++) {
            float4 a = *(const float4*)(Aptr + (size_t)r * 64 * K + k0);
            float4 w = *(const float4*)(Wptr + (size_t)r * 64 * K + k0);
            int row = lrow + r * 64;
            As[lk + 0][row] = a.x; As[lk + 1][row] = a.y;
            As[lk + 2][row] = a.z; As[lk + 3][row] = a.w;
            Bs[lk + 0][row] = w.x; Bs[lk + 1][row] = w.y;
            Bs[lk + 2][row] = w.z; Bs[lk + 3][row] = w.w;
        }
        __syncthreads();
#pragma unroll
        for (int kk = 0; kk < 16; kk++) {
            float a[8], b[8];
            *(float4*)&a[0] = *(const float4*)&As[kk][tr * 8];
            *(float4*)&a[4] = *(const float4*)&As[kk][tr * 8 + 4];
            *(float4*)&b[0] = *(const float4*)&Bs[kk][tc * 8];
            *(float4*)&b[4] = *(const float4*)&Bs[kk][tc * 8 + 4];
#pragma unroll
            for (int i = 0; i < 8; i++)
#pragma unroll
                for (int j = 0; j < 8; j++) acc[i][j] = fmaf(a[i], b[j], acc[i][j]);
        }
        __syncthreads();
    }

#pragma unroll
    for (int i = 0; i < 8; i++) {
        int row = bm + tr * 8 + i;
#pragma unroll
        for (int j = 0; j < 8; j++) {
            int col = bn + tc * 8 + j;
            float v = acc[i][j] + bias[col];
            if (EP == EP_BIAS_GELU)
                v = 0.5f * v * (1.f + erff(v * 0.70710678118654752f));
            if (EP == EP_BIAS_RES)
                v += res[(size_t)row * N + col];
            C[(size_t)row * N + col] = v;
        }
    }
}

// ---------------- Windowed attention: one block per (window, head) ---------
__global__ __launch_bounds__(256) void attn_kernel(const float* __restrict__ qkv,
                                                   const float* __restrict__ bias_table,
                                                   float* __restrict__ o) {
    __shared__ float qs[49 * 32];
    __shared__ float ks[49 * 32];
    __shared__ float vs[49 * 32];
    __shared__ float Ss[49 * 49];

    int bw   = blockIdx.x >> 3;
    int head = blockIdx.x & 7;
    int b  = bw >> 6;
    int wi = bw & 63;
    int wh = wi >> 3;
    int ww = wi & 7;
    int tid = threadIdx.x;

    // load q (pre-scaled), k, v tiles
    for (int idx = tid; idx < 49 * 32; idx += 256) {
        int n = idx >> 5, d = idx & 31;
        int t = b * 3136 + (wh * 7 + n / 7) * 56 + ww * 7 + (n % 7);
        const float* base = qkv + (size_t)t * 768 + head * 32 + d;
        qs[idx] = base[0] * 0.17677669529663687f;  // 1/sqrt(32)
        ks[idx] = base[256];
        vs[idx] = base[512];
    }
    __syncthreads();

    // scores + relative position bias
    for (int idx = tid; idx < 49 * 49; idx += 256) {
        int i = idx / 49, j = idx - i * 49;
        float s = 0.f;
#pragma unroll
        for (int d = 0; d < 32; d++) s = fmaf(qs[i * 32 + d], ks[j * 32 + d], s);
        int ri = i / 7, ci = i % 7, rj = j / 7, cj = j % 7;
        int rel = (ri - rj + 6) * 13 + (ci - cj + 6);
        Ss[idx] = s + bias_table[rel * 8 + head];
    }
    __syncthreads();

    // softmax: warp per row
    int warp = tid >> 5, lane = tid & 31;
    for (int i = warp; i < 49; i += 8) {
        float v0 = Ss[i * 49 + lane];
        float v1 = (lane + 32 < 49) ? Ss[i * 49 + lane + 32] : -1e30f;
        float m = fmaxf(v0, v1);
#pragma unroll
        for (int off = 16; off; off >>= 1) m = fmaxf(m, __shfl_xor_sync(0xffffffffu, m, off));
        float e0 = expf(v0 - m);
        float e1 = (lane + 32 < 49) ? expf(v1 - m) : 0.f;
        float s = e0 + e1;
#pragma unroll
        for (int off = 16; off; off >>= 1) s += __shfl_xor_sync(0xffffffffu, s, off);
        float inv = 1.f / s;
        Ss[i * 49 + lane] = e0 * inv;
        if (lane + 32 < 49) Ss[i * 49 + lane + 32] = e1 * inv;
    }
    __syncthreads();

    // O = P * V, scatter directly to token layout
    for (int idx = tid; idx < 49 * 32; idx += 256) {
        int i = idx >> 5, d = idx & 31;
        float s = 0.f;
#pragma unroll
        for (int j = 0; j < 49; j++) s = fmaf(Ss[i * 49 + j], vs[j * 32 + d], s);
        int t = b * 3136 + (wh * 7 + i / 7) * 56 + ww * 7 + (i % 7);
        o[(size_t)t * 256 + head * 32 + d] = s;
    }
}

// ---------------- launch ----------------
extern "C" void kernel_launch(void* const* d_in, const int* in_sizes, int n_in,
                              void* d_out, int out_size) {
    const float* x          = (const float*)d_in[0];
    const float* norm1_g    = (const float*)d_in[1];
    const float* norm1_b    = (const float*)d_in[2];
    const float* qkv_w      = (const float*)d_in[3];
    const float* qkv_b      = (const float*)d_in[4];
    const float* bias_table = (const float*)d_in[5];
    const float* proj_w     = (const float*)d_in[6];
    const float* proj_b     = (const float*)d_in[7];
    const float* norm2_g    = (const float*)d_in[8];
    const float* norm2_b    = (const float*)d_in[9];
    const float* ffn_w1     = (const float*)d_in[10];
    const float* ffn_b1     = (const float*)d_in[11];
    const float* ffn_w2     = (const float*)d_in[12];
    const float* ffn_b2     = (const float*)d_in[13];
    float* out = (float*)d_out;

    float *y, *qkv, *o, *x1, *z, *h1;
    cudaGetSymbolAddress((void**)&y,   g_y);
    cudaGetSymbolAddress((void**)&qkv, g_qkv);
    cudaGetSymbolAddress((void**)&o,   g_o);
    cudaGetSymbolAddress((void**)&x1,  g_x1);
    cudaGetSymbolAddress((void**)&z,   g_z);
    cudaGetSymbolAddress((void**)&h1,  g_h1);

    const int MT = TOK;           // 100352 = 784*128

    // 1) LN1
    ln_kernel<<<TOK / 8, 256>>>(x, norm1_g, norm1_b, y);

    // 2) QKV: [T,256] x [768,256]^T -> [T,768]
    sgemm_nt<EP_BIAS><<<dim3(768 / 128, MT / 128), 256>>>(y, qkv_w, qkv_b, nullptr,
                                                          qkv, MT, 768, 256);

    // 3) windowed attention, one block per (window, head)
    attn_kernel<<<NWIN * HEADS, 256>>>(qkv, bias_table, o);

    // 4) proj + shortcut residual -> x1
    sgemm_nt<EP_BIAS_RES><<<dim3(256 / 128, MT / 128), 256>>>(o, proj_w, proj_b, x,
                                                              x1, MT, 256, 256);

    // 5) LN2
    ln_kernel<<<TOK / 8, 256>>>(x1, norm2_g, norm2_b, z);

    // 6) FFN1 + exact GELU
    sgemm_nt<EP_BIAS_GELU><<<dim3(HID / 128, MT / 128), 256>>>(z, ffn_w1, ffn_b1, nullptr,
                                                               h1, MT, HID, 256);

    // 7) FFN2 + residual(x1) -> out
    sgemm_nt<EP_BIAS_RES><<<dim3(256 / 128, MT / 128), 256>>>(h1, ffn_w2, ffn_b2, x1,
                                                              out, MT, 256, HID);
}

// round 2
// speedup vs baseline: 1.8886x; 1.8886x over previous
#include <cuda_runtime.h>
#include <math.h>

// ---------------- problem constants ----------------
#define NB 32
#define HH 56
#define WW 56
#define CD 256
#define TOK (NB*HH*WW)          // 100352 tokens
#define HEADS 8
#define HDIM 32
#define HID 1024
#define WS 7
#define NWIN (TOK/(WS*WS))      // 2048 windows

// ---------------- scratch (static device globals; no runtime alloc) -------
__device__ float g_y   [(size_t)TOK * CD];
__device__ float g_qkv [(size_t)TOK * 3 * CD];
__device__ float g_o   [(size_t)TOK * CD];
__device__ float g_x1  [(size_t)TOK * CD];
__device__ float g_z   [(size_t)TOK * CD];
__device__ float g_h1  [(size_t)TOK * HID];

// ---------------- LayerNorm: one warp per token (256 channels) -------------
__global__ __launch_bounds__(256) void ln_kernel(const float* __restrict__ in,
                                                 const float* __restrict__ g,
                                                 const float* __restrict__ b,
                                                 float* __restrict__ out) {
    int warp = (blockIdx.x * blockDim.x + threadIdx.x) >> 5;
    int lane = threadIdx.x & 31;
    if (warp >= TOK) return;
    const float* row = in + (size_t)warp * CD;
    float v[8];
    float s = 0.f;
#pragma unroll
    for (int k = 0; k < 8; k++) { v[k] = row[lane + k * 32]; s += v[k]; }
#pragma unroll
    for (int o = 16; o; o >>= 1) s += __shfl_xor_sync(0xffffffffu, s, o);
    float mean = s * (1.f / 256.f);
    float ss = 0.f;
#pragma unroll
    for (int k = 0; k < 8; k++) { float d = v[k] - mean; ss += d * d; }
#pragma unroll
    for (int o = 16; o; o >>= 1) ss += __shfl_xor_sync(0xffffffffu, ss, o);
    float inv = rsqrtf(ss * (1.f / 256.f) + 1e-5f);
    float* orow = out + (size_t)warp * CD;
#pragma unroll
    for (int k = 0; k < 8; k++) {
        int c = lane + k * 32;
        orow[c] = (v[k] - mean) * inv * g[c] + b[c];
    }
}

// ---------------- tf32 helpers ----------------
__device__ __forceinline__ float to_tf32(float x) {
    unsigned u;
    asm("cvt.rna.tf32.f32 %0, %1;" : "=r"(u) : "f"(x));
    return __uint_as_float(u);
}

__device__ __forceinline__ void mma_tf32(float* c, const float* a, const float* b) {
    asm volatile(
        "mma.sync.aligned.m16n8k8.row.col.f32.tf32.tf32.f32 "
        "{%0,%1,%2,%3}, {%4,%5,%6,%7}, {%8,%9}, {%0,%1,%2,%3};\n"
        : "+f"(c[0]), "+f"(c[1]), "+f"(c[2]), "+f"(c[3])
        : "r"(__float_as_uint(a[0])), "r"(__float_as_uint(a[1])),
          "r"(__float_as_uint(a[2])), "r"(__float_as_uint(a[3])),
          "r"(__float_as_uint(b[0])), "r"(__float_as_uint(b[1])));
}

// ---------------- tf32 tensor-core GEMM: C = A[M,K] * W[N,K]^T ------------
// Exact tiles: M%128==0, N%128==0, K%16==0 (true for all calls).
enum { EP_BIAS = 0, EP_BIAS_RES = 1, EP_BIAS_GELU = 2 };

#define BK 16
#define SSTR 20   // smem row stride (floats): conflict-free for frag loads

template <int EP>
__global__ __launch_bounds__(256) void tgemm(const float* __restrict__ A,
                                             const float* __restrict__ W,
                                             const float* __restrict__ bias,
                                             const float* __restrict__ res,
                                             float* __restrict__ C,
                                             int M, int N, int K) {
    __shared__ float As[2][128][SSTR];
    __shared__ float Bs[2][128][SSTR];

    int tid = threadIdx.x;
    int bm = blockIdx.y * 128;
    int bn = blockIdx.x * 128;
    int warp = tid >> 5, lane = tid & 31;
    int g = lane >> 2, tig = lane & 3;
    int warpM = warp >> 2;       // 0..1  (64 rows each)
    int warpN = warp & 3;        // 0..3  (32 cols each)

    int lrow = tid >> 2;         // 0..63
    int lcol = (tid & 3) << 2;   // 0,4,8,12

    const float* Aptr = A + (size_t)(bm + lrow) * K + lcol;
    const float* Wptr = W + (size_t)(bn + lrow) * K + lcol;

    float acc[4][4][4];
#pragma unroll
    for (int i = 0; i < 4; i++)
#pragma unroll
        for (int j = 0; j < 4; j++)
#pragma unroll
            for (int t = 0; t < 4; t++) acc[i][j][t] = 0.f;

    // preload tile 0
    {
        float4 a0 = *(const float4*)(Aptr);
        float4 a1 = *(const float4*)(Aptr + (size_t)64 * K);
        float4 w0 = *(const float4*)(Wptr);
        float4 w1 = *(const float4*)(Wptr + (size_t)64 * K);
        *(float4*)&As[0][lrow][lcol] =
            make_float4(to_tf32(a0.x), to_tf32(a0.y), to_tf32(a0.z), to_tf32(a0.w));
        *(float4*)&As[0][lrow + 64][lcol] =
            make_float4(to_tf32(a1.x), to_tf32(a1.y), to_tf32(a1.z), to_tf32(a1.w));
        *(float4*)&Bs[0][lrow][lcol] =
            make_float4(to_tf32(w0.x), to_tf32(w0.y), to_tf32(w0.z), to_tf32(w0.w));
        *(float4*)&Bs[0][lrow + 64][lcol] =
            make_float4(to_tf32(w1.x), to_tf32(w1.y), to_tf32(w1.z), to_tf32(w1.w));
    }
    __syncthreads();

    int niter = K / BK;
    for (int it = 0; it < niter; it++) {
        int cur = it & 1;
        // prefetch next tile
        float4 a0, a1, w0, w1;
        if (it + 1 < niter) {
            int k0 = (it + 1) * BK;
            a0 = *(const float4*)(Aptr + k0);
            a1 = *(const float4*)(Aptr + (size_t)64 * K + k0);
            w0 = *(const float4*)(Wptr + k0);
            w1 = *(const float4*)(Wptr + (size_t)64 * K + k0);
        }

        // compute on current buffer: two k=8 steps
#pragma unroll
        for (int s = 0; s < 2; s++) {
            float af[4][4], bf[4][2];
#pragma unroll
            for (int mt = 0; mt < 4; mt++) {
                int m = warpM * 64 + mt * 16 + g;
                int k = s * 8 + tig;
                af[mt][0] = As[cur][m][k];
                af[mt][1] = As[cur][m + 8][k];
                af[mt][2] = As[cur][m][k + 4];
                af[mt][3] = As[cur][m + 8][k + 4];
            }
#pragma unroll
            for (int nt = 0; nt < 4; nt++) {
                int n = warpN * 32 + nt * 8 + g;
                int k = s * 8 + tig;
                bf[nt][0] = Bs[cur][n][k];
                bf[nt][1] = Bs[cur][n][k + 4];
            }
#pragma unroll
            for (int mt = 0; mt < 4; mt++)
#pragma unroll
                for (int nt = 0; nt < 4; nt++)
                    mma_tf32(acc[mt][nt], af[mt], bf[nt]);
        }

        if (it + 1 < niter) {
            int nxt = cur ^ 1;
            *(float4*)&As[nxt][lrow][lcol] =
                make_float4(to_tf32(a0.x), to_tf32(a0.y), to_tf32(a0.z), to_tf32(a0.w));
            *(float4*)&As[nxt][lrow + 64][lcol] =
                make_float4(to_tf32(a1.x), to_tf32(a1.y), to_tf32(a1.z), to_tf32(a1.w));
            *(float4*)&Bs[nxt][lrow][lcol] =
                make_float4(to_tf32(w0.x), to_tf32(w0.y), to_tf32(w0.z), to_tf32(w0.w));
            *(float4*)&Bs[nxt][lrow + 64][lcol] =
                make_float4(to_tf32(w1.x), to_tf32(w1.y), to_tf32(w1.z), to_tf32(w1.w));
        }
        __syncthreads();
    }

    // epilogue
#pragma unroll
    for (int mt = 0; mt < 4; mt++) {
        int r0 = bm + warpM * 64 + mt * 16 + g;
#pragma unroll
        for (int nt = 0; nt < 4; nt++) {
            int c = bn + warpN * 32 + nt * 8 + 2 * tig;
            float2 bv = *(const float2*)&bias[c];
            float v0 = acc[mt][nt][0] + bv.x;
            float v1 = acc[mt][nt][1] + bv.y;
            float v2 = acc[mt][nt][2] + bv.x;
            float v3 = acc[mt][nt][3] + bv.y;
            if (EP == EP_BIAS_GELU) {
                v0 = 0.5f * v0 * (1.f + erff(v0 * 0.70710678118654752f));
                v1 = 0.5f * v1 * (1.f + erff(v1 * 0.70710678118654752f));
                v2 = 0.5f * v2 * (1.f + erff(v2 * 0.70710678118654752f));
                v3 = 0.5f * v3 * (1.f + erff(v3 * 0.70710678118654752f));
            }
            if (EP == EP_BIAS_RES) {
                float2 r0v = *(const float2*)&res[(size_t)r0 * N + c];
                float2 r1v = *(const float2*)&res[(size_t)(r0 + 8) * N + c];
                v0 += r0v.x; v1 += r0v.y; v2 += r1v.x; v3 += r1v.y;
            }
            *(float2*)&C[(size_t)r0 * N + c] = make_float2(v0, v1);
            *(float2*)&C[(size_t)(r0 + 8) * N + c] = make_float2(v2, v3);
        }
    }
}

// ---------------- Windowed attention: one block per (window, head) ---------
__global__ __launch_bounds__(256) void attn_kernel(const float* __restrict__ qkv,
                                                   const float* __restrict__ bias_table,
                                                   float* __restrict__ o) {
    __shared__ float qs[49 * 32];
    __shared__ float ks[49 * 32];
    __shared__ float vs[49 * 32];
    __shared__ float Ss[49 * 49];

    int bw   = blockIdx.x >> 3;
    int head = blockIdx.x & 7;
    int b  = bw >> 6;
    int wi = bw & 63;
    int wh = wi >> 3;
    int ww = wi & 7;
    int tid = threadIdx.x;

    for (int idx = tid; idx < 49 * 32; idx += 256) {
        int n = idx >> 5, d = idx & 31;
        int t = b * 3136 + (wh * 7 + n / 7) * 56 + ww * 7 + (n % 7);
        const float* base = qkv + (size_t)t * 768 + head * 32 + d;
        qs[idx] = base[0] * 0.17677669529663687f;
        ks[idx] = base[256];
        vs[idx] = base[512];
    }
    __syncthreads();

    for (int idx = tid; idx < 49 * 49; idx += 256) {
        int i = idx / 49, j = idx - i * 49;
        float s = 0.f;
#pragma unroll
        for (int d = 0; d < 32; d++) s = fmaf(qs[i * 32 + d], ks[j * 32 + d], s);
        int ri = i / 7, ci = i % 7, rj = j / 7, cj = j % 7;
        int rel = (ri - rj + 6) * 13 + (ci - cj + 6);
        Ss[idx] = s + bias_table[rel * 8 + head];
    }
    __syncthreads();

    int warp = tid >> 5, lane = tid & 31;
    for (int i = warp; i < 49; i += 8) {
        float v0 = Ss[i * 49 + lane];
        float v1 = (lane + 32 < 49) ? Ss[i * 49 + lane + 32] : -1e30f;
        float m = fmaxf(v0, v1);
#pragma unroll
        for (int off = 16; off; off >>= 1) m = fmaxf(m, __shfl_xor_sync(0xffffffffu, m, off));
        float e0 = expf(v0 - m);
        float e1 = (lane + 32 < 49) ? expf(v1 - m) : 0.f;
        float s = e0 + e1;
#pragma unroll
        for (int off = 16; off; off >>= 1) s += __shfl_xor_sync(0xffffffffu, s, off);
        float inv = 1.f / s;
        Ss[i * 49 + lane] = e0 * inv;
        if (lane + 32 < 49) Ss[i * 49 + lane + 32] = e1 * inv;
    }
    __syncthreads();

    for (int idx = tid; idx < 49 * 32; idx += 256) {
        int i = idx >> 5, d = idx & 31;
        float s = 0.f;
#pragma unroll
        for (int j = 0; j < 49; j++) s = fmaf(Ss[i * 49 + j], vs[j * 32 + d], s);
        int t = b * 3136 + (wh * 7 + i / 7) * 56 + ww * 7 + (i % 7);
        o[(size_t)t * 256 + head * 32 + d] = s;
    }
}

// ---------------- launch ----------------
extern "C" void kernel_launch(void* const* d_in, const int* in_sizes, int n_in,
                              void* d_out, int out_size) {
    const float* x          = (const float*)d_in[0];
    const float* norm1_g    = (const float*)d_in[1];
    const float* norm1_b    = (const float*)d_in[2];
    const float* qkv_w      = (const float*)d_in[3];
    const float* qkv_b      = (const float*)d_in[4];
    const float* bias_table = (const float*)d_in[5];
    const float* proj_w     = (const float*)d_in[6];
    const float* proj_b     = (const float*)d_in[7];
    const float* norm2_g    = (const float*)d_in[8];
    const float* norm2_b    = (const float*)d_in[9];
    const float* ffn_w1     = (const float*)d_in[10];
    const float* ffn_b1     = (const float*)d_in[11];
    const float* ffn_w2     = (const float*)d_in[12];
    const float* ffn_b2     = (const float*)d_in[13];
    float* out = (float*)d_out;

    float *y, *qkv, *o, *x1, *z, *h1;
    cudaGetSymbolAddress((void**)&y,   g_y);
    cudaGetSymbolAddress((void**)&qkv, g_qkv);
    cudaGetSymbolAddress((void**)&o,   g_o);
    cudaGetSymbolAddress((void**)&x1,  g_x1);
    cudaGetSymbolAddress((void**)&z,   g_z);
    cudaGetSymbolAddress((void**)&h1,  g_h1);

    const int MT = TOK;  // 100352 = 784*128

    ln_kernel<<<TOK / 8, 256>>>(x, norm1_g, norm1_b, y);

    tgemm<EP_BIAS><<<dim3(768 / 128, MT / 128), 256>>>(y, qkv_w, qkv_b, nullptr,
                                                       qkv, MT, 768, 256);

    attn_kernel<<<NWIN * HEADS, 256>>>(qkv, bias_table, o);

    tgemm<EP_BIAS_RES><<<dim3(256 / 128, MT / 128), 256>>>(o, proj_w, proj_b, x,
                                                           x1, MT, 256, 256);

    ln_kernel<<<TOK / 8, 256>>>(x1, norm2_g, norm2_b, z);

    tgemm<EP_BIAS_GELU><<<dim3(HID / 128, MT / 128), 256>>>(z, ffn_w1, ffn_b1, nullptr,
                                                            h1, MT, HID, 256);

    tgemm<EP_BIAS_RES><<<dim3(256 / 128, MT / 128), 256>>>(h1, ffn_w2, ffn_b2, x1,
                                                           out, MT, 256, HID);
}

// round 3
// speedup vs baseline: 3.2018x; 1.6953x over previous
#include <cuda_runtime.h>
#include <math.h>

// ---------------- problem constants ----------------
#define NB 32
#define HH 56
#define WW 56
#define CD 256
#define TOK (NB*HH*WW)          // 100352 tokens
#define HEADS 8
#define HDIM 32
#define HID 1024
#define WS 7
#define NWIN (TOK/(WS*WS))      // 2048 windows

// ---------------- scratch (static device globals; no runtime alloc) -------
__device__ float g_y   [(size_t)TOK * CD];
__device__ float g_qkv [(size_t)TOK * 3 * CD];
__device__ float g_o   [(size_t)TOK * CD];
__device__ float g_x1  [(size_t)TOK * CD];
__device__ float g_z   [(size_t)TOK * CD];
__device__ float g_h1  [(size_t)TOK * HID];
__device__ float g_bias[8 * 64 * 64];            // expanded rel-pos bias (+mask)

// ---------------- LayerNorm: one warp per token (256 channels) -------------
__global__ __launch_bounds__(256) void ln_kernel(const float* __restrict__ in,
                                                 const float* __restrict__ g,
                                                 const float* __restrict__ b,
                                                 float* __restrict__ out) {
    int warp = (blockIdx.x * blockDim.x + threadIdx.x) >> 5;
    int lane = threadIdx.x & 31;
    if (warp >= TOK) return;
    const float* row = in + (size_t)warp * CD;
    float v[8];
    float s = 0.f;
#pragma unroll
    for (int k = 0; k < 8; k++) { v[k] = row[lane + k * 32]; s += v[k]; }
#pragma unroll
    for (int o = 16; o; o >>= 1) s += __shfl_xor_sync(0xffffffffu, s, o);
    float mean = s * (1.f / 256.f);
    float ss = 0.f;
#pragma unroll
    for (int k = 0; k < 8; k++) { float d = v[k] - mean; ss += d * d; }
#pragma unroll
    for (int o = 16; o; o >>= 1) ss += __shfl_xor_sync(0xffffffffu, ss, o);
    float inv = rsqrtf(ss * (1.f / 256.f) + 1e-5f);
    float* orow = out + (size_t)warp * CD;
#pragma unroll
    for (int k = 0; k < 8; k++) {
        int c = lane + k * 32;
        orow[c] = (v[k] - mean) * inv * g[c] + b[c];
    }
}

// ---------------- tf32 helpers ----------------
__device__ __forceinline__ float to_tf32(float x) {
    unsigned u;
    asm("cvt.rna.tf32.f32 %0, %1;" : "=r"(u) : "f"(x));
    return __uint_as_float(u);
}

__device__ __forceinline__ void mma_tf32(float* c, const float* a, const float* b) {
    asm volatile(
        "mma.sync.aligned.m16n8k8.row.col.f32.tf32.tf32.f32 "
        "{%0,%1,%2,%3}, {%4,%5,%6,%7}, {%8,%9}, {%0,%1,%2,%3};\n"
        : "+f"(c[0]), "+f"(c[1]), "+f"(c[2]), "+f"(c[3])
        : "r"(__float_as_uint(a[0])), "r"(__float_as_uint(a[1])),
          "r"(__float_as_uint(a[2])), "r"(__float_as_uint(a[3])),
          "r"(__float_as_uint(b[0])), "r"(__float_as_uint(b[1])));
}

// ---------------- tf32 tensor-core GEMM: C = A[M,K] * W[N,K]^T ------------
enum { EP_BIAS = 0, EP_BIAS_RES = 1, EP_BIAS_GELU = 2 };

#define BK 16
#define SSTR 20

template <int EP>
__global__ __launch_bounds__(256) void tgemm(const float* __restrict__ A,
                                             const float* __restrict__ W,
                                             const float* __restrict__ bias,
                                             const float* __restrict__ res,
                                             float* __restrict__ C,
                                             int M, int N, int K) {
    __shared__ float As[2][128][SSTR];
    __shared__ float Bs[2][128][SSTR];

    int tid = threadIdx.x;
    int bm = blockIdx.y * 128;
    int bn = blockIdx.x * 128;
    int warp = tid >> 5, lane = tid & 31;
    int g = lane >> 2, tig = lane & 3;
    int warpM = warp >> 2;
    int warpN = warp & 3;

    int lrow = tid >> 2;
    int lcol = (tid & 3) << 2;

    const float* Aptr = A + (size_t)(bm + lrow) * K + lcol;
    const float* Wptr = W + (size_t)(bn + lrow) * K + lcol;

    float acc[4][4][4];
#pragma unroll
    for (int i = 0; i < 4; i++)
#pragma unroll
        for (int j = 0; j < 4; j++)
#pragma unroll
            for (int t = 0; t < 4; t++) acc[i][j][t] = 0.f;

    {
        float4 a0 = *(const float4*)(Aptr);
        float4 a1 = *(const float4*)(Aptr + (size_t)64 * K);
        float4 w0 = *(const float4*)(Wptr);
        float4 w1 = *(const float4*)(Wptr + (size_t)64 * K);
        *(float4*)&As[0][lrow][lcol] =
            make_float4(to_tf32(a0.x), to_tf32(a0.y), to_tf32(a0.z), to_tf32(a0.w));
        *(float4*)&As[0][lrow + 64][lcol] =
            make_float4(to_tf32(a1.x), to_tf32(a1.y), to_tf32(a1.z), to_tf32(a1.w));
        *(float4*)&Bs[0][lrow][lcol] =
            make_float4(to_tf32(w0.x), to_tf32(w0.y), to_tf32(w0.z), to_tf32(w0.w));
        *(float4*)&Bs[0][lrow + 64][lcol] =
            make_float4(to_tf32(w1.x), to_tf32(w1.y), to_tf32(w1.z), to_tf32(w1.w));
    }
    __syncthreads();

    int niter = K / BK;
    for (int it = 0; it < niter; it++) {
        int cur = it & 1;
        float4 a0, a1, w0, w1;
        if (it + 1 < niter) {
            int k0 = (it + 1) * BK;
            a0 = *(const float4*)(Aptr + k0);
            a1 = *(const float4*)(Aptr + (size_t)64 * K + k0);
            w0 = *(const float4*)(Wptr + k0);
            w1 = *(const float4*)(Wptr + (size_t)64 * K + k0);
        }

#pragma unroll
        for (int s = 0; s < 2; s++) {
            float af[4][4], bf[4][2];
#pragma unroll
            for (int mt = 0; mt < 4; mt++) {
                int m = warpM * 64 + mt * 16 + g;
                int k = s * 8 + tig;
                af[mt][0] = As[cur][m][k];
                af[mt][1] = As[cur][m + 8][k];
                af[mt][2] = As[cur][m][k + 4];
                af[mt][3] = As[cur][m + 8][k + 4];
            }
#pragma unroll
            for (int nt = 0; nt < 4; nt++) {
                int n = warpN * 32 + nt * 8 + g;
                int k = s * 8 + tig;
                bf[nt][0] = Bs[cur][n][k];
                bf[nt][1] = Bs[cur][n][k + 4];
            }
#pragma unroll
            for (int mt = 0; mt < 4; mt++)
#pragma unroll
                for (int nt = 0; nt < 4; nt++)
                    mma_tf32(acc[mt][nt], af[mt], bf[nt]);
        }

        if (it + 1 < niter) {
            int nxt = cur ^ 1;
            *(float4*)&As[nxt][lrow][lcol] =
                make_float4(to_tf32(a0.x), to_tf32(a0.y), to_tf32(a0.z), to_tf32(a0.w));
            *(float4*)&As[nxt][lrow + 64][lcol] =
                make_float4(to_tf32(a1.x), to_tf32(a1.y), to_tf32(a1.z), to_tf32(a1.w));
            *(float4*)&Bs[nxt][lrow][lcol] =
                make_float4(to_tf32(w0.x), to_tf32(w0.y), to_tf32(w0.z), to_tf32(w0.w));
            *(float4*)&Bs[nxt][lrow + 64][lcol] =
                make_float4(to_tf32(w1.x), to_tf32(w1.y), to_tf32(w1.z), to_tf32(w1.w));
        }
        __syncthreads();
    }

#pragma unroll
    for (int mt = 0; mt < 4; mt++) {
        int r0 = bm + warpM * 64 + mt * 16 + g;
#pragma unroll
        for (int nt = 0; nt < 4; nt++) {
            int c = bn + warpN * 32 + nt * 8 + 2 * tig;
            float2 bv = *(const float2*)&bias[c];
            float v0 = acc[mt][nt][0] + bv.x;
            float v1 = acc[mt][nt][1] + bv.y;
            float v2 = acc[mt][nt][2] + bv.x;
            float v3 = acc[mt][nt][3] + bv.y;
            if (EP == EP_BIAS_GELU) {
                v0 = 0.5f * v0 * (1.f + erff(v0 * 0.70710678118654752f));
                v1 = 0.5f * v1 * (1.f + erff(v1 * 0.70710678118654752f));
                v2 = 0.5f * v2 * (1.f + erff(v2 * 0.70710678118654752f));
                v3 = 0.5f * v3 * (1.f + erff(v3 * 0.70710678118654752f));
            }
            if (EP == EP_BIAS_RES) {
                float2 r0v = *(const float2*)&res[(size_t)r0 * N + c];
                float2 r1v = *(const float2*)&res[(size_t)(r0 + 8) * N + c];
                v0 += r0v.x; v1 += r0v.y; v2 += r1v.x; v3 += r1v.y;
            }
            *(float2*)&C[(size_t)r0 * N + c] = make_float2(v0, v1);
            *(float2*)&C[(size_t)(r0 + 8) * N + c] = make_float2(v2, v3);
        }
    }
}

// ---------------- expand rel-pos bias into [8][64][64] with col mask -------
__global__ void bias_expand(const float* __restrict__ table,
                            float* __restrict__ bf) {
    int idx = blockIdx.x * 256 + threadIdx.x;
    if (idx >= 8 * 64 * 64) return;
    int h = idx >> 12;
    int r = (idx >> 6) & 63;
    int c = idx & 63;
    float v;
    if (c >= 49) v = -1e30f;
    else if (r >= 49) v = 0.f;
    else {
        int ri = r / 7, ci = r % 7, rj = c / 7, cj = c % 7;
        int rel = (ri - rj + 6) * 13 + (ci - cj + 6);
        v = table[rel * 8 + h];
    }
    bf[idx] = v;
}

// ---------------- tensor-core windowed attention ---------------------------
// One 128-thread block per (window, head). n padded 49->64.
#define QP 36   // Q/K smem pitch (floats): bank = 4g+tig, conflict-free frags
#define PP 68   // P and V^T smem pitch
__global__ __launch_bounds__(128) void attn_mma(const float* __restrict__ qkv,
                                                const float* __restrict__ bias_full,
                                                float* __restrict__ o) {
    // SQ/SK region (2*64*36 = 4608 floats) is reused for P (64*68 = 4352)
    __shared__ float smem[64 * QP * 2 + 32 * PP];
    float* SQ = smem;
    float* SK = smem + 64 * QP;
    float* SP = smem;                 // aliases SQ/SK after S is computed
    float* VT = smem + 64 * QP * 2;   // V transposed [32][64], pitch PP

    int bw   = blockIdx.x >> 3;
    int head = blockIdx.x & 7;
    int b  = bw >> 6;
    int wi = bw & 63;
    int wh = wi >> 3;
    int ww = wi & 7;
    int tid  = threadIdx.x;
    int warp = tid >> 5, lane = tid & 31;
    int g = lane >> 2, tig = lane & 3;

    // ---- load Q (scaled), K as [64][32] tf32, pitch QP ----
    for (int idx = tid; idx < 512; idx += 128) {
        int n = idx >> 3, f = (idx & 7) << 2;
        float4 qv = make_float4(0.f, 0.f, 0.f, 0.f);
        float4 kv = make_float4(0.f, 0.f, 0.f, 0.f);
        if (n < 49) {
            int t = b * 3136 + (wh * 7 + n / 7) * 56 + ww * 7 + (n % 7);
            const float* base = qkv + (size_t)t * 768 + head * 32 + f;
            qv = *(const float4*)(base);
            kv = *(const float4*)(base + 256);
            const float sc = 0.17677669529663687f;
            qv.x *= sc; qv.y *= sc; qv.z *= sc; qv.w *= sc;
        }
        *(float4*)&SQ[n * QP + f] =
            make_float4(to_tf32(qv.x), to_tf32(qv.y), to_tf32(qv.z), to_tf32(qv.w));
        *(float4*)&SK[n * QP + f] =
            make_float4(to_tf32(kv.x), to_tf32(kv.y), to_tf32(kv.z), to_tf32(kv.w));
    }
    // ---- load V transposed: VT[d][n], pitch PP ----
    for (int idx = tid; idx < 2048; idx += 128) {
        int n = idx >> 5, d = idx & 31;
        float val = 0.f;
        if (n < 49) {
            int t = b * 3136 + (wh * 7 + n / 7) * 56 + ww * 7 + (n % 7);
            val = qkv[(size_t)t * 768 + head * 32 + 512 + d];
        }
        VT[d * PP + n] = to_tf32(val);
    }
    __syncthreads();

    // ---- S = Q*K^T : each warp does 16 rows x 64 cols ----
    float accS[8][4];
#pragma unroll
    for (int nt = 0; nt < 8; nt++)
#pragma unroll
        for (int t = 0; t < 4; t++) accS[nt][t] = 0.f;

    int wrow = warp * 16;
#pragma unroll
    for (int ks = 0; ks < 4; ks++) {
        int kk = ks * 8 + tig;
        float a[4];
        a[0] = SQ[(wrow + g) * QP + kk];
        a[1] = SQ[(wrow + g + 8) * QP + kk];
        a[2] = SQ[(wrow + g) * QP + kk + 4];
        a[3] = SQ[(wrow + g + 8) * QP + kk + 4];
#pragma unroll
        for (int nt = 0; nt < 8; nt++) {
            float bf[2];
            bf[0] = SK[(nt * 8 + g) * QP + kk];
            bf[1] = SK[(nt * 8 + g) * QP + kk + 4];
            mma_tf32(accS[nt], a, bf);
        }
    }

    // ---- bias + masked softmax (register-resident) ----
    int r0 = wrow + g, r1 = wrow + g + 8;
    const float* bh = bias_full + head * 4096;
    float m0 = -1e30f, m1 = -1e30f;
#pragma unroll
    for (int nt = 0; nt < 8; nt++) {
        float2 b0 = *(const float2*)(bh + r0 * 64 + nt * 8 + 2 * tig);
        float2 b1 = *(const float2*)(bh + r1 * 64 + nt * 8 + 2 * tig);
        accS[nt][0] += b0.x; accS[nt][1] += b0.y;
        accS[nt][2] += b1.x; accS[nt][3] += b1.y;
        m0 = fmaxf(m0, fmaxf(accS[nt][0], accS[nt][1]));
        m1 = fmaxf(m1, fmaxf(accS[nt][2], accS[nt][3]));
    }
    m0 = fmaxf(m0, __shfl_xor_sync(0xffffffffu, m0, 1));
    m0 = fmaxf(m0, __shfl_xor_sync(0xffffffffu, m0, 2));
    m1 = fmaxf(m1, __shfl_xor_sync(0xffffffffu, m1, 1));
    m1 = fmaxf(m1, __shfl_xor_sync(0xffffffffu, m1, 2));

    float s0 = 0.f, s1 = 0.f;
#pragma unroll
    for (int nt = 0; nt < 8; nt++) {
        accS[nt][0] = __expf(accS[nt][0] - m0);
        accS[nt][1] = __expf(accS[nt][1] - m0);
        accS[nt][2] = __expf(accS[nt][2] - m1);
        accS[nt][3] = __expf(accS[nt][3] - m1);
        s0 += accS[nt][0] + accS[nt][1];
        s1 += accS[nt][2] + accS[nt][3];
    }
    s0 += __shfl_xor_sync(0xffffffffu, s0, 1);
    s0 += __shfl_xor_sync(0xffffffffu, s0, 2);
    s1 += __shfl_xor_sync(0xffffffffu, s1, 1);
    s1 += __shfl_xor_sync(0xffffffffu, s1, 2);
    float i0 = 1.f / s0, i1 = 1.f / s1;

    // all warps must finish reading SQ/SK before P overwrites them
    __syncthreads();
#pragma unroll
    for (int nt = 0; nt < 8; nt++) {
        *(float2*)&SP[r0 * PP + nt * 8 + 2 * tig] =
            make_float2(to_tf32(accS[nt][0] * i0), to_tf32(accS[nt][1] * i0));
        *(float2*)&SP[r1 * PP + nt * 8 + 2 * tig] =
            make_float2(to_tf32(accS[nt][2] * i1), to_tf32(accS[nt][3] * i1));
    }
    __syncthreads();

    // ---- O = P * V : 16 rows x 32 cols per warp ----
    float accO[4][4];
#pragma unroll
    for (int nt = 0; nt < 4; nt++)
#pragma unroll
        for (int t = 0; t < 4; t++) accO[nt][t] = 0.f;

#pragma unroll
    for (int ks = 0; ks < 8; ks++) {
        int kk = ks * 8 + tig;
        float a[4];
        a[0] = SP[(wrow + g) * PP + kk];
        a[1] = SP[(wrow + g + 8) * PP + kk];
        a[2] = SP[(wrow + g) * PP + kk + 4];
        a[3] = SP[(wrow + g + 8) * PP + kk + 4];
#pragma unroll
        for (int nt = 0; nt < 4; nt++) {
            float bf[2];
            bf[0] = VT[(nt * 8 + g) * PP + kk];
            bf[1] = VT[(nt * 8 + g) * PP + kk + 4];
            mma_tf32(accO[nt], a, bf);
        }
    }

    // ---- scatter to token layout ----
    if (r0 < 49) {
        int t = b * 3136 + (wh * 7 + r0 / 7) * 56 + ww * 7 + (r0 % 7);
        float* op = o + (size_t)t * 256 + head * 32;
#pragma unroll
        for (int nt = 0; nt < 4; nt++)
            *(float2*)(op + nt * 8 + 2 * tig) = make_float2(accO[nt][0], accO[nt][1]);
    }
    if (r1 < 49) {
        int t = b * 3136 + (wh * 7 + r1 / 7) * 56 + ww * 7 + (r1 % 7);
        float* op = o + (size_t)t * 256 + head * 32;
#pragma unroll
        for (int nt = 0; nt < 4; nt++)
            *(float2*)(op + nt * 8 + 2 * tig) = make_float2(accO[nt][2], accO[nt][3]);
    }
}

// ---------------- launch ----------------
extern "C" void kernel_launch(void* const* d_in, const int* in_sizes, int n_in,
                              void* d_out, int out_size) {
    const float* x          = (const float*)d_in[0];
    const float* norm1_g    = (const float*)d_in[1];
    const float* norm1_b    = (const float*)d_in[2];
    const float* qkv_w      = (const float*)d_in[3];
    const float* qkv_b      = (const float*)d_in[4];
    const float* bias_table = (const float*)d_in[5];
    const float* proj_w     = (const float*)d_in[6];
    const float* proj_b     = (const float*)d_in[7];
    const float* norm2_g    = (const float*)d_in[8];
    const float* norm2_b    = (const float*)d_in[9];
    const float* ffn_w1     = (const float*)d_in[10];
    const float* ffn_b1     = (const float*)d_in[11];
    const float* ffn_w2     = (const float*)d_in[12];
    const float* ffn_b2     = (const float*)d_in[13];
    float* out = (float*)d_out;

    float *y, *qkv, *o, *x1, *z, *h1, *bf;
    cudaGetSymbolAddress((void**)&y,   g_y);
    cudaGetSymbolAddress((void**)&qkv, g_qkv);
    cudaGetSymbolAddress((void**)&o,   g_o);
    cudaGetSymbolAddress((void**)&x1,  g_x1);
    cudaGetSymbolAddress((void**)&z,   g_z);
    cudaGetSymbolAddress((void**)&h1,  g_h1);
    cudaGetSymbolAddress((void**)&bf,  g_bias);

    const int MT = TOK;  // 100352 = 784*128

    bias_expand<<<(8 * 64 * 64 + 255) / 256, 256>>>(bias_table, bf);

    ln_kernel<<<TOK / 8, 256>>>(x, norm1_g, norm1_b, y);

    tgemm<EP_BIAS><<<dim3(768 / 128, MT / 128), 256>>>(y, qkv_w, qkv_b, nullptr,
                                                       qkv, MT, 768, 256);

    attn_mma<<<NWIN * HEADS, 128>>>(qkv, bf, o);

    tgemm<EP_BIAS_RES><<<dim3(256 / 128, MT / 128), 256>>>(o, proj_w, proj_b, x,
                                                           x1, MT, 256, 256);

    ln_kernel<<<TOK / 8, 256>>>(x1, norm2_g, norm2_b, z);

    tgemm<EP_BIAS_GELU><<<dim3(HID / 128, MT / 128), 256>>>(z, ffn_w1, ffn_b1, nullptr,
                                                            h1, MT, HID, 256);

    tgemm<EP_BIAS_RES><<<dim3(256 / 128, MT / 128), 256>>>(h1, ffn_w2, ffn_b2, x1,
                                                           out, MT, 256, HID);
}

// round 4
// speedup vs baseline: 5.6684x; 1.7704x over previous
#include <cuda_runtime.h>
#include <cuda_bf16.h>
#include <math.h>

// ---------------- problem constants ----------------
#define NB 32
#define HH 56
#define WW 56
#define CD 256
#define TOK (NB*HH*WW)          // 100352 tokens
#define HEADS 8
#define HDIM 32
#define HID 1024
#define WS 7
#define NWIN (TOK/(WS*WS))      // 2048 windows

typedef __nv_bfloat16 bf16;
typedef __nv_bfloat162 bf162;

// ---------------- scratch (static device globals; no runtime alloc) -------
__device__ __align__(16) bf16  g_y   [(size_t)TOK * CD];
__device__ __align__(16) bf16  g_qkv [(size_t)TOK * 3 * CD];
__device__ __align__(16) bf16  g_o   [(size_t)TOK * CD];
__device__ __align__(16) float g_x1  [(size_t)TOK * CD];
__device__ __align__(16) bf16  g_z   [(size_t)TOK * CD];
__device__ __align__(16) bf16  g_h1  [(size_t)TOK * HID];
__device__ __align__(16) float g_bias[8 * 64 * 64];
// bf16 weight copies
__device__ __align__(16) bf16  g_wq[3 * CD * CD];
__device__ __align__(16) bf16  g_wp[CD * CD];
__device__ __align__(16) bf16  g_w1[HID * CD];
__device__ __align__(16) bf16  g_w2[CD * HID];

// ---------------- fp32 -> bf16 weight conversion ---------------------------
__global__ void wconv(const float* __restrict__ src, bf16* __restrict__ dst, int n4) {
    int i = blockIdx.x * 256 + threadIdx.x;
    if (i >= n4) return;
    float4 v = ((const float4*)src)[i];
    *(bf162*)&dst[i * 4]     = __floats2bfloat162_rn(v.x, v.y);
    *(bf162*)&dst[i * 4 + 2] = __floats2bfloat162_rn(v.z, v.w);
}

// ---------------- LayerNorm: warp per token, bf16 out ----------------------
__global__ __launch_bounds__(256) void ln_kernel(const float* __restrict__ in,
                                                 const float* __restrict__ g,
                                                 const float* __restrict__ b,
                                                 bf16* __restrict__ out) {
    int warp = (blockIdx.x * blockDim.x + threadIdx.x) >> 5;
    int lane = threadIdx.x & 31;
    if (warp >= TOK) return;
    const float* row = in + (size_t)warp * CD;
    float v[8];
    *(float4*)&v[0] = ((const float4*)row)[lane * 2];
    *(float4*)&v[4] = ((const float4*)row)[lane * 2 + 1];
    float s = 0.f;
#pragma unroll
    for (int k = 0; k < 8; k++) s += v[k];
#pragma unroll
    for (int o = 16; o; o >>= 1) s += __shfl_xor_sync(0xffffffffu, s, o);
    float mean = s * (1.f / 256.f);
    float ss = 0.f;
#pragma unroll
    for (int k = 0; k < 8; k++) { float d = v[k] - mean; ss += d * d; }
#pragma unroll
    for (int o = 16; o; o >>= 1) ss += __shfl_xor_sync(0xffffffffu, ss, o);
    float inv = rsqrtf(ss * (1.f / 256.f) + 1e-5f);
    float gg[8], bb[8];
    *(float4*)&gg[0] = ((const float4*)g)[lane * 2];
    *(float4*)&gg[4] = ((const float4*)g)[lane * 2 + 1];
    *(float4*)&bb[0] = ((const float4*)b)[lane * 2];
    *(float4*)&bb[4] = ((const float4*)b)[lane * 2 + 1];
    bf16* orow = out + (size_t)warp * CD + lane * 8;
#pragma unroll
    for (int k = 0; k < 4; k++) {
        float v0 = (v[2*k]   - mean) * inv * gg[2*k]   + bb[2*k];
        float v1 = (v[2*k+1] - mean) * inv * gg[2*k+1] + bb[2*k+1];
        *(bf162*)&orow[2*k] = __floats2bfloat162_rn(v0, v1);
    }
}

// ---------------- mma / cp.async helpers -----------------------------------
__device__ __forceinline__ void mma_bf16(float* c, const unsigned* a, const unsigned* b) {
    asm volatile(
        "mma.sync.aligned.m16n8k16.row.col.f32.bf16.bf16.f32 "
        "{%0,%1,%2,%3}, {%4,%5,%6,%7}, {%8,%9}, {%0,%1,%2,%3};\n"
        : "+f"(c[0]), "+f"(c[1]), "+f"(c[2]), "+f"(c[3])
        : "r"(a[0]), "r"(a[1]), "r"(a[2]), "r"(a[3]), "r"(b[0]), "r"(b[1]));
}

__device__ __forceinline__ void cpa16(void* smem_dst, const void* gsrc) {
    unsigned s = (unsigned)__cvta_generic_to_shared(smem_dst);
    asm volatile("cp.async.cg.shared.global [%0], [%1], 16;\n" :: "r"(s), "l"(gsrc));
}

// ---------------- bf16 tensor-core GEMM: C = A[M,K] * W[N,K]^T -------------
// Exact tiles: M%128==0, N%128==0, K%32==0.
enum { EP_BIAS = 0, EP_BIAS_RES = 1, EP_BIAS_GELU = 2 };

#define SP40 40   // smem pitch (halves) — conflict-free fragment loads

template <int EP, typename OutT>
__global__ __launch_bounds__(256) void hgemm(const bf16* __restrict__ A,
                                             const bf16* __restrict__ W,
                                             const float* __restrict__ bias,
                                             const float* __restrict__ res,
                                             OutT* __restrict__ C,
                                             int M, int N, int K) {
    __shared__ bf16 As[2][128][SP40];
    __shared__ bf16 Bs[2][128][SP40];

    int tid = threadIdx.x;
    int bm = blockIdx.y * 128;
    int bn = blockIdx.x * 128;
    int warp = tid >> 5, lane = tid & 31;
    int g = lane >> 2, tig = lane & 3;
    int warpM = warp >> 2;       // 0..1 (64 rows)
    int warpN = warp & 3;        // 0..3 (32 cols)

    int lrow = tid >> 2;         // 0..63
    int lcol = (tid & 3) * 8;    // halves: 0,8,16,24

    const bf16* Aptr = A + (size_t)(bm + lrow) * K + lcol;
    const bf16* Wptr = W + (size_t)(bn + lrow) * K + lcol;

    float acc[4][4][4];
#pragma unroll
    for (int i = 0; i < 4; i++)
#pragma unroll
        for (int j = 0; j < 4; j++)
#pragma unroll
            for (int t = 0; t < 4; t++) acc[i][j][t] = 0.f;

    // prologue: stage tile 0
    cpa16(&As[0][lrow][lcol],      Aptr);
    cpa16(&As[0][lrow + 64][lcol], Aptr + (size_t)64 * K);
    cpa16(&Bs[0][lrow][lcol],      Wptr);
    cpa16(&Bs[0][lrow + 64][lcol], Wptr + (size_t)64 * K);
    asm volatile("cp.async.commit_group;\n");

    int niter = K / 32;
    for (int it = 0; it < niter; it++) {
        int cur = it & 1;
        if (it + 1 < niter) {
            int k0 = (it + 1) * 32;
            int nxt = cur ^ 1;
            cpa16(&As[nxt][lrow][lcol],      Aptr + k0);
            cpa16(&As[nxt][lrow + 64][lcol], Aptr + (size_t)64 * K + k0);
            cpa16(&Bs[nxt][lrow][lcol],      Wptr + k0);
            cpa16(&Bs[nxt][lrow + 64][lcol], Wptr + (size_t)64 * K + k0);
            asm volatile("cp.async.commit_group;\n");
            asm volatile("cp.async.wait_group 1;\n");
        } else {
            asm volatile("cp.async.wait_group 0;\n");
        }
        __syncthreads();

#pragma unroll
        for (int s = 0; s < 2; s++) {
            int kk = s * 16 + 2 * tig;
            unsigned af[4][4], bfr[4][2];
#pragma unroll
            for (int mt = 0; mt < 4; mt++) {
                int m = warpM * 64 + mt * 16 + g;
                af[mt][0] = *(const unsigned*)&As[cur][m][kk];
                af[mt][1] = *(const unsigned*)&As[cur][m + 8][kk];
                af[mt][2] = *(const unsigned*)&As[cur][m][kk + 8];
                af[mt][3] = *(const unsigned*)&As[cur][m + 8][kk + 8];
            }
#pragma unroll
            for (int nt = 0; nt < 4; nt++) {
                int n = warpN * 32 + nt * 8 + g;
                bfr[nt][0] = *(const unsigned*)&Bs[cur][n][kk];
                bfr[nt][1] = *(const unsigned*)&Bs[cur][n][kk + 8];
            }
#pragma unroll
            for (int mt = 0; mt < 4; mt++)
#pragma unroll
                for (int nt = 0; nt < 4; nt++)
                    mma_bf16(acc[mt][nt], af[mt], bfr[nt]);
        }
        __syncthreads();
    }

    // epilogue
#pragma unroll
    for (int mt = 0; mt < 4; mt++) {
        int r0 = bm + warpM * 64 + mt * 16 + g;
#pragma unroll
        for (int nt = 0; nt < 4; nt++) {
            int c = bn + warpN * 32 + nt * 8 + 2 * tig;
            float2 bv = *(const float2*)&bias[c];
            float v0 = acc[mt][nt][0] + bv.x;
            float v1 = acc[mt][nt][1] + bv.y;
            float v2 = acc[mt][nt][2] + bv.x;
            float v3 = acc[mt][nt][3] + bv.y;
            if (EP == EP_BIAS_GELU) {
                v0 = 0.5f * v0 * (1.f + erff(v0 * 0.70710678118654752f));
                v1 = 0.5f * v1 * (1.f + erff(v1 * 0.70710678118654752f));
                v2 = 0.5f * v2 * (1.f + erff(v2 * 0.70710678118654752f));
                v3 = 0.5f * v3 * (1.f + erff(v3 * 0.70710678118654752f));
            }
            if (EP == EP_BIAS_RES) {
                float2 r0v = *(const float2*)&res[(size_t)r0 * N + c];
                float2 r1v = *(const float2*)&res[(size_t)(r0 + 8) * N + c];
                v0 += r0v.x; v1 += r0v.y; v2 += r1v.x; v3 += r1v.y;
            }
            if (sizeof(OutT) == 2) {
                *(bf162*)((bf16*)C + (size_t)r0 * N + c) = __floats2bfloat162_rn(v0, v1);
                *(bf162*)((bf16*)C + (size_t)(r0 + 8) * N + c) = __floats2bfloat162_rn(v2, v3);
            } else {
                *(float2*)((float*)C + (size_t)r0 * N + c) = make_float2(v0, v1);
                *(float2*)((float*)C + (size_t)(r0 + 8) * N + c) = make_float2(v2, v3);
            }
        }
    }
}

// ---------------- expand rel-pos bias into [8][64][64] with col mask -------
__global__ void bias_expand(const float* __restrict__ table,
                            float* __restrict__ bf) {
    int idx = blockIdx.x * 256 + threadIdx.x;
    if (idx >= 8 * 64 * 64) return;
    int h = idx >> 12;
    int r = (idx >> 6) & 63;
    int c = idx & 63;
    float v;
    if (c >= 49) v = -1e30f;
    else if (r >= 49) v = 0.f;
    else {
        int ri = r / 7, ci = r % 7, rj = c / 7, cj = c % 7;
        int rel = (ri - rj + 6) * 13 + (ci - cj + 6);
        v = table[rel * 8 + h];
    }
    bf[idx] = v;
}

// ---------------- bf16 tensor-core windowed attention ----------------------
// One 128-thread block per (window, head). n padded 49->64.
#define QP 40   // Q/K pitch (halves)
#define PP 72   // P / V^T pitch (halves)
__global__ __launch_bounds__(128) void attn_mma(const bf16* __restrict__ qkv,
                                                const float* __restrict__ bias_full,
                                                bf16* __restrict__ o) {
    __shared__ bf16 smem[64 * QP * 2 + 32 * PP];   // SQ|SK (aliased by SP) + VT
    __shared__ int  TOF[64];
    bf16* SQ = smem;
    bf16* SK = smem + 64 * QP;
    bf16* SPm = smem;                  // P[64][PP], aliases SQ/SK
    bf16* VT = smem + 64 * QP * 2;     // V^T [32][64] pitch PP

    int bw   = blockIdx.x >> 3;
    int head = blockIdx.x & 7;
    int b  = bw >> 6;
    int wi = bw & 63;
    int wh = wi >> 3;
    int ww = wi & 7;
    int tid  = threadIdx.x;
    int warp = tid >> 5, lane = tid & 31;
    int g = lane >> 2, tig = lane & 3;

    if (tid < 64) {
        int n = tid;
        int r = n / 7, c = n - r * 7;
        TOF[n] = (n < 49) ? (b * 3136 + (wh * 7 + r) * 56 + ww * 7 + c) : 0;
    }
    __syncthreads();

    // ---- load Q, K as [64][32] halves (raw, int4), V transposed ----
    const int4 zero4 = make_int4(0, 0, 0, 0);
    for (int idx = tid; idx < 256; idx += 128) {
        int n = idx >> 2, seg = (idx & 3) * 8;
        int4 qv = zero4, kv = zero4;
        if (n < 49) {
            const bf16* base = qkv + (size_t)TOF[n] * 768 + head * 32 + seg;
            qv = *(const int4*)(base);
            kv = *(const int4*)(base + 256);
        }
        *(int4*)&SQ[n * QP + seg] = qv;
        *(int4*)&SK[n * QP + seg] = kv;
    }
    for (int idx = tid; idx < 2048; idx += 128) {
        int n = idx >> 5, d = idx & 31;
        bf16 val = __float2bfloat16(0.f);
        if (n < 49) val = qkv[(size_t)TOF[n] * 768 + 512 + head * 32 + d];
        VT[d * PP + n] = val;
    }
    __syncthreads();

    // ---- S = Q*K^T : warp does 16 rows x 64 cols ----
    float accS[8][4];
#pragma unroll
    for (int nt = 0; nt < 8; nt++)
#pragma unroll
        for (int t = 0; t < 4; t++) accS[nt][t] = 0.f;

    int wrow = warp * 16;
#pragma unroll
    for (int ks = 0; ks < 2; ks++) {
        int kk = ks * 16 + 2 * tig;
        unsigned a[4];
        a[0] = *(const unsigned*)&SQ[(wrow + g) * QP + kk];
        a[1] = *(const unsigned*)&SQ[(wrow + g + 8) * QP + kk];
        a[2] = *(const unsigned*)&SQ[(wrow + g) * QP + kk + 8];
        a[3] = *(const unsigned*)&SQ[(wrow + g + 8) * QP + kk + 8];
#pragma unroll
        for (int nt = 0; nt < 8; nt++) {
            unsigned bfr[2];
            bfr[0] = *(const unsigned*)&SK[(nt * 8 + g) * QP + kk];
            bfr[1] = *(const unsigned*)&SK[(nt * 8 + g) * QP + kk + 8];
            mma_bf16(accS[nt], a, bfr);
        }
    }

    // ---- scale + bias + masked softmax (register-resident) ----
    const float sc = 0.17677669529663687f;   // 1/sqrt(32)
    int r0 = wrow + g, r1 = wrow + g + 8;
    const float* bh = bias_full + head * 4096;
    float m0 = -1e30f, m1 = -1e30f;
#pragma unroll
    for (int nt = 0; nt < 8; nt++) {
        float2 b0 = *(const float2*)(bh + r0 * 64 + nt * 8 + 2 * tig);
        float2 b1 = *(const float2*)(bh + r1 * 64 + nt * 8 + 2 * tig);
        accS[nt][0] = accS[nt][0] * sc + b0.x;
        accS[nt][1] = accS[nt][1] * sc + b0.y;
        accS[nt][2] = accS[nt][2] * sc + b1.x;
        accS[nt][3] = accS[nt][3] * sc + b1.y;
        m0 = fmaxf(m0, fmaxf(accS[nt][0], accS[nt][1]));
        m1 = fmaxf(m1, fmaxf(accS[nt][2], accS[nt][3]));
    }
    m0 = fmaxf(m0, __shfl_xor_sync(0xffffffffu, m0, 1));
    m0 = fmaxf(m0, __shfl_xor_sync(0xffffffffu, m0, 2));
    m1 = fmaxf(m1, __shfl_xor_sync(0xffffffffu, m1, 1));
    m1 = fmaxf(m1, __shfl_xor_sync(0xffffffffu, m1, 2));

    float s0 = 0.f, s1 = 0.f;
#pragma unroll
    for (int nt = 0; nt < 8; nt++) {
        accS[nt][0] = __expf(accS[nt][0] - m0);
        accS[nt][1] = __expf(accS[nt][1] - m0);
        accS[nt][2] = __expf(accS[nt][2] - m1);
        accS[nt][3] = __expf(accS[nt][3] - m1);
        s0 += accS[nt][0] + accS[nt][1];
        s1 += accS[nt][2] + accS[nt][3];
    }
    s0 += __shfl_xor_sync(0xffffffffu, s0, 1);
    s0 += __shfl_xor_sync(0xffffffffu, s0, 2);
    s1 += __shfl_xor_sync(0xffffffffu, s1, 1);
    s1 += __shfl_xor_sync(0xffffffffu, s1, 2);
    float i0 = 1.f / s0, i1 = 1.f / s1;

    __syncthreads();   // SQ/SK reads complete before P overwrites
#pragma unroll
    for (int nt = 0; nt < 8; nt++) {
        *(bf162*)&SPm[r0 * PP + nt * 8 + 2 * tig] =
            __floats2bfloat162_rn(accS[nt][0] * i0, accS[nt][1] * i0);
        *(bf162*)&SPm[r1 * PP + nt * 8 + 2 * tig] =
            __floats2bfloat162_rn(accS[nt][2] * i1, accS[nt][3] * i1);
    }
    __syncthreads();

    // ---- O = P * V : 16 rows x 32 cols per warp ----
    float accO[4][4];
#pragma unroll
    for (int nt = 0; nt < 4; nt++)
#pragma unroll
        for (int t = 0; t < 4; t++) accO[nt][t] = 0.f;

#pragma unroll
    for (int ks = 0; ks < 4; ks++) {
        int kk = ks * 16 + 2 * tig;
        unsigned a[4];
        a[0] = *(const unsigned*)&SPm[(wrow + g) * PP + kk];
        a[1] = *(const unsigned*)&SPm[(wrow + g + 8) * PP + kk];
        a[2] = *(const unsigned*)&SPm[(wrow + g) * PP + kk + 8];
        a[3] = *(const unsigned*)&SPm[(wrow + g + 8) * PP + kk + 8];
#pragma unroll
        for (int nt = 0; nt < 4; nt++) {
            unsigned bfr[2];
            bfr[0] = *(const unsigned*)&VT[(nt * 8 + g) * PP + kk];
            bfr[1] = *(const unsigned*)&VT[(nt * 8 + g) * PP + kk + 8];
            mma_bf16(accO[nt], a, bfr);
        }
    }

    // ---- scatter to token layout (bf16) ----
    if (r0 < 49) {
        bf16* op = o + (size_t)TOF[r0] * 256 + head * 32;
#pragma unroll
        for (int nt = 0; nt < 4; nt++)
            *(bf162*)(op + nt * 8 + 2 * tig) = __floats2bfloat162_rn(accO[nt][0], accO[nt][1]);
    }
    if (r1 < 49) {
        bf16* op = o + (size_t)TOF[r1] * 256 + head * 32;
#pragma unroll
        for (int nt = 0; nt < 4; nt++)
            *(bf162*)(op + nt * 8 + 2 * tig) = __floats2bfloat162_rn(accO[nt][2], accO[nt][3]);
    }
}

// ---------------- launch ----------------
extern "C" void kernel_launch(void* const* d_in, const int* in_sizes, int n_in,
                              void* d_out, int out_size) {
    const float* x          = (const float*)d_in[0];
    const float* norm1_g    = (const float*)d_in[1];
    const float* norm1_b    = (const float*)d_in[2];
    const float* qkv_w      = (const float*)d_in[3];
    const float* qkv_b      = (const float*)d_in[4];
    const float* bias_table = (const float*)d_in[5];
    const float* proj_w     = (const float*)d_in[6];
    const float* proj_b     = (const float*)d_in[7];
    const float* norm2_g    = (const float*)d_in[8];
    const float* norm2_b    = (const float*)d_in[9];
    const float* ffn_w1     = (const float*)d_in[10];
    const float* ffn_b1     = (const float*)d_in[11];
    const float* ffn_w2     = (const float*)d_in[12];
    const float* ffn_b2     = (const float*)d_in[13];
    float* out = (float*)d_out;

    bf16 *y, *qkv, *o, *z, *h1, *wq, *wp, *w1, *w2;
    float *x1, *bf;
    cudaGetSymbolAddress((void**)&y,   g_y);
    cudaGetSymbolAddress((void**)&qkv, g_qkv);
    cudaGetSymbolAddress((void**)&o,   g_o);
    cudaGetSymbolAddress((void**)&x1,  g_x1);
    cudaGetSymbolAddress((void**)&z,   g_z);
    cudaGetSymbolAddress((void**)&h1,  g_h1);
    cudaGetSymbolAddress((void**)&bf,  g_bias);
    cudaGetSymbolAddress((void**)&wq,  g_wq);
    cudaGetSymbolAddress((void**)&wp,  g_wp);
    cudaGetSymbolAddress((void**)&w1,  g_w1);
    cudaGetSymbolAddress((void**)&w2,  g_w2);

    const int MT = TOK;  // 100352 = 784*128

    wconv<<<(3 * CD * CD / 4 + 255) / 256, 256>>>(qkv_w, wq, 3 * CD * CD / 4);
    wconv<<<(CD * CD / 4 + 255) / 256, 256>>>(proj_w, wp, CD * CD / 4);
    wconv<<<(HID * CD / 4 + 255) / 256, 256>>>(ffn_w1, w1, HID * CD / 4);
    wconv<<<(CD * HID / 4 + 255) / 256, 256>>>(ffn_w2, w2, CD * HID / 4);
    bias_expand<<<(8 * 64 * 64 + 255) / 256, 256>>>(bias_table, bf);

    ln_kernel<<<TOK / 8, 256>>>(x, norm1_g, norm1_b, y);

    hgemm<EP_BIAS, bf16><<<dim3(768 / 128, MT / 128), 256>>>(y, wq, qkv_b, nullptr,
                                                             qkv, MT, 768, 256);

    attn_mma<<<NWIN * HEADS, 128>>>(qkv, bf, o);

    hgemm<EP_BIAS_RES, float><<<dim3(256 / 128, MT / 128), 256>>>(o, wp, proj_b, x,
                                                                  x1, MT, 256, 256);

    ln_kernel<<<TOK / 8, 256>>>(x1, norm2_g, norm2_b, z);

    hgemm<EP_BIAS_GELU, bf16><<<dim3(HID / 128, MT / 128), 256>>>(z, w1, ffn_b1, nullptr,
                                                                  h1, MT, HID, 256);

    hgemm<EP_BIAS_RES, float><<<dim3(256 / 128, MT / 128), 256>>>(h1, w2, ffn_b2, x1,
                                                                  out, MT, 256, 1024);
}